// round 4
// baseline (speedup 1.0000x reference)
#include <cuda_runtime.h>

// ---------------- problem constants (fixed by the dataset) ----------------
#define NA    4096
#define NB    4000
#define NANG  8000
#define NAC   4000
#define ND    12000
#define NDC   6000
#define NI    2000
#define TILE  128
#define NTILE (NA / TILE)                    // 32
#define NPAIRBLK (NTILE * (NTILE + 1) / 2)   // 528
#define COULF 332.33f
#define EPSF  1e-12f

#define ANG_OFF   (NB)                       // 4000
#define ANGC_OFF  (ANG_OFF + NANG)           // 12000
#define DIH_OFF   (ANGC_OFF + NAC)           // 16000
#define DIHC_OFF  (DIH_OFF + ND)             // 28000
#define IMP_OFF   (DIHC_OFF + NDC)           // 34000
#define CORR_OFF  (IMP_OFF + NI)             // 36000
#define NCORR     (NB + NANG)                // 12000
#define TOT_BONDED (CORR_OFF + NCORR)        // 48000
#define NBONDBLK  ((TOT_BONDED + TILE - 1) / TILE)  // 375
#define NBLK_MAIN (NPAIRBLK + NBONDBLK)             // 903

#define HASH_BITS 15
#define HASH_SIZE (1 << HASH_BITS)           // 32768 entries, ~12000 used

// ---------------- device scratch (static, zero-init; restored to zero each call) ----------------
__device__ double       g_acc;
__device__ unsigned int g_count;
__device__ unsigned int g_hash[HASH_SIZE];

// ---------------- math helpers ----------------
__device__ __forceinline__ float rsqrt_mufu(float x) {
    // MUFU.RSQ + one Newton step: full fp32 accuracy, MUFU pipe never binding here.
    float y;
    asm("rsqrt.approx.f32 %0, %1;" : "=f"(y) : "f"(x));
    return y * fmaf(-0.5f * x, y * y, 1.5f);
}

struct f3 { float x, y, z; };
__device__ __forceinline__ f3 ldp(const float* p, int i) {
    return { p[3 * i], p[3 * i + 1], p[3 * i + 2] };
}
__device__ __forceinline__ f3 f3sub(f3 a, f3 b) { return { a.x - b.x, a.y - b.y, a.z - b.z }; }
__device__ __forceinline__ float f3dot(f3 a, f3 b) { return a.x * b.x + a.y * b.y + a.z * b.z; }
__device__ __forceinline__ f3 f3cross(f3 a, f3 b) {
    return { a.y * b.z - a.z * b.y, a.z * b.x - a.x * b.z, a.x * b.y - a.y * b.x };
}

__device__ __forceinline__ float angle3(f3 p0, f3 p1, f3 p2) {
    f3 u = f3sub(p0, p1);
    f3 v = f3sub(p2, p1);
    float c = f3dot(u, v) / sqrtf(f3dot(u, u) * f3dot(v, v) + EPSF);
    c = fminf(fmaxf(c, -1.0f + 1e-7f), 1.0f - 1e-7f);
    return acosf(c);
}

__device__ __forceinline__ float dihedral_phi(f3 p0, f3 p1, f3 p2, f3 p3) {
    f3 b1 = f3sub(p1, p0);
    f3 b2 = f3sub(p2, p1);
    f3 b3 = f3sub(p3, p2);
    f3 n1 = f3cross(b1, b2);
    f3 n2 = f3cross(b2, b3);
    float bl = sqrtf(f3dot(b2, b2) + EPSF);
    f3 b2n = { b2.x / bl, b2.y / bl, b2.z / bl };
    float yv = f3dot(f3cross(n1, b2n), n2);
    float xv = f3dot(n1, n2);
    return atan2f(yv, xv);
}

// LJ + Coulomb pair energy computed from the raw input arrays (matches pair loop)
__device__ __forceinline__ float pair_energy_raw(
    int i, int j,
    const float* __restrict__ pos, const float* __restrict__ q,
    const float* __restrict__ eps, const float* __restrict__ sig)
{
    float dx = pos[3 * i]     - pos[3 * j];
    float dy = pos[3 * i + 1] - pos[3 * j + 1];
    float dz = pos[3 * i + 2] - pos[3 * j + 2];
    float r2 = fmaf(dx, dx, fmaf(dy, dy, fmaf(dz, dz, EPSF)));
    float rinv = rsqrt_mufu(r2);
    float sr  = (0.5f * sig[i] + 0.5f * sig[j]) * rinv;
    float sr2 = sr * sr;
    float sr6 = sr2 * sr2 * sr2;
    float t   = fmaf(sr6, sr6, -sr6);                 // sr12 - sr6
    float ee  = (2.0f * sqrtf(eps[i])) * (2.0f * sqrtf(eps[j]));
    float qq  = (q[i] * sqrtf(COULF)) * (q[j] * sqrtf(COULF));
    return fmaf(ee, t, qq * rinv);
}

// ---------------- bonded + correction thread body ----------------
__device__ __forceinline__ float bonded_body(
    int gid,
    const float* __restrict__ pos, const float* __restrict__ q,
    const float* __restrict__ eps, const float* __restrict__ sig,
    const float* __restrict__ sb_mask,
    const float* __restrict__ bond_c, const float* __restrict__ angle_c,
    const float* __restrict__ anglec_c, const float* __restrict__ dih_c,
    const float* __restrict__ dihc_c, const float* __restrict__ imp_c,
    const int* __restrict__ bond_i, const int* __restrict__ angle_i,
    const int* __restrict__ anglec_i, const int* __restrict__ dih_i,
    const int* __restrict__ dihc_i, const int* __restrict__ imp_i)
{
    float e = 0.0f;
    if (gid < ANG_OFF) {
        const int* b = bond_i + 3 * gid;
        int i = b[0], j = b[1], ty = b[2];
        f3 d = f3sub(ldp(pos, i), ldp(pos, j));
        float r = sqrtf(f3dot(d, d) + EPSF);
        float dr = r - bond_c[2 * ty + 1];
        e = bond_c[2 * ty] * dr * dr;
    } else if (gid < ANGC_OFF) {
        int k = gid - ANG_OFF;
        const int* a = angle_i + 4 * k;
        int ty = a[3];
        float th = angle3(ldp(pos, a[0]), ldp(pos, a[1]), ldp(pos, a[2]));
        float dth = th - angle_c[2 * ty + 1];
        e = angle_c[2 * ty] * dth * dth;
    } else if (gid < DIH_OFF) {
        int k = gid - ANGC_OFF;
        const int* a = anglec_i + 4 * k;
        int ty = a[3];
        f3 p0 = ldp(pos, a[0]), p1 = ldp(pos, a[1]), p2 = ldp(pos, a[2]);
        float th = angle3(p0, p1, p2);
        f3 d02 = f3sub(p0, p2);
        float r13 = sqrtf(f3dot(d02, d02) + EPSF);
        const float* c = anglec_c + 4 * ty;
        float dth = th - c[1];
        float dr  = r13 - c[3];
        e = c[0] * dth * dth + c[2] * dr * dr;
    } else if (gid < DIHC_OFF) {
        int k = gid - DIH_OFF;
        const int* a = dih_i + 5 * k;
        int ty = a[4];
        float phi = dihedral_phi(ldp(pos, a[0]), ldp(pos, a[1]),
                                 ldp(pos, a[2]), ldp(pos, a[3]));
        float c = cosf(phi);
        const float* A = dih_c + 5 * ty;
        e = A[0] + c * (A[1] + c * (A[2] + c * (A[3] + c * A[4])));
    } else if (gid < IMP_OFF) {
        int k = gid - DIHC_OFF;
        const int* a = dihc_i + 5 * k;
        int ty = a[4];
        float phi = dihedral_phi(ldp(pos, a[0]), ldp(pos, a[1]),
                                 ldp(pos, a[2]), ldp(pos, a[3]));
        const float* c = dihc_c + 4 * ty;
        e = c[0] * (1.0f + cosf(c[1] * phi - c[2]));
    } else if (gid < CORR_OFF) {
        int k = gid - IMP_OFF;
        const int* a = imp_i + 5 * k;
        int ty = a[4];
        float chi = dihedral_phi(ldp(pos, a[0]), ldp(pos, a[1]),
                                 ldp(pos, a[2]), ldp(pos, a[3]));
        float d = chi - imp_c[2 * ty + 1];
        e = imp_c[2 * ty] * d * d;
    } else if (gid < TOT_BONDED) {
        // mask==0 correction: candidates = bond pairs + angle 1-3 pairs.
        // Subtract each distinct masked pair's energy exactly once (hash-set dedup).
        int c = gid - CORR_OFF;
        int iu, iv;
        if (c < NB) { iu = bond_i[3 * c]; iv = bond_i[3 * c + 1]; }
        else        { int a = c - NB; iu = angle_i[4 * a]; iv = angle_i[4 * a + 2]; }
        if (iu != iv) {
            int lo = min(iu, iv), hi = max(iu, iv);
            if (sb_mask[(size_t)lo * NA + hi] == 0.0f) {
                unsigned key = ((unsigned)lo << 12) | (unsigned)hi;   // nonzero (lo<hi)
                unsigned h = (key * 2654435761u) >> (32 - HASH_BITS);
                bool first = false;
                for (;;) {
                    unsigned old = atomicCAS(&g_hash[h], 0u, key);
                    if (old == 0u) { first = true; break; }
                    if (old == key) break;
                    h = (h + 1) & (HASH_SIZE - 1);
                }
                if (first) e = -pair_energy_raw(lo, hi, pos, q, eps, sig);
            }
        }
    }
    return e;
}

// ---------------- the single fused kernel ----------------
__global__ void __launch_bounds__(TILE) k_main(
    float* __restrict__ out,
    const float* __restrict__ pos, const float* __restrict__ q,
    const float* __restrict__ eps, const float* __restrict__ sig,
    const float* __restrict__ sb_mask,
    const float* __restrict__ bond_c, const float* __restrict__ angle_c,
    const float* __restrict__ anglec_c, const float* __restrict__ dih_c,
    const float* __restrict__ dihc_c, const float* __restrict__ imp_c,
    const int* __restrict__ bond_i, const int* __restrict__ angle_i,
    const int* __restrict__ anglec_i, const int* __restrict__ dih_i,
    const int* __restrict__ dihc_i, const int* __restrict__ imp_i)
{
    float acc = 0.0f;

    if (blockIdx.x < NPAIRBLK) {
        // ---- all-pairs LJ + Coulomb over one 128x128 tile ----
        __shared__ float4 spq[TILE];    // xj, yj, zj, qj*sqrt(C)
        __shared__ float2 sls[TILE];    // 0.5*sig_j, 2*sqrt(eps_j)

        int t = blockIdx.x;
        int bi = 0, rowlen = NTILE;
        while (t >= rowlen) { t -= rowlen; rowlen--; bi++; }
        int bj = bi + t;

        int li = threadIdx.x;
        int gi = bi * TILE + li;
        int gj = bj * TILE + li;

        // derive per-atom data inline (replaces the init kernel)
        float4 pqi = make_float4(pos[3 * gi], pos[3 * gi + 1], pos[3 * gi + 2],
                                 q[gi] * sqrtf(COULF));
        float2 lsi = make_float2(0.5f * sig[gi], 2.0f * sqrtf(eps[gi]));
        spq[li] = make_float4(pos[3 * gj], pos[3 * gj + 1], pos[3 * gj + 2],
                              q[gj] * sqrtf(COULF));
        sls[li] = make_float2(0.5f * sig[gj], 2.0f * sqrtf(eps[gj]));
        __syncthreads();

        if (bi != bj) {
            // clean path: every (li, j) pair counts
#pragma unroll 8
            for (int j = 0; j < TILE; j++) {
                float4 pqj = spq[j];
                float2 lsj = sls[j];
                float dx = pqi.x - pqj.x;
                float dy = pqi.y - pqj.y;
                float dz = pqi.z - pqj.z;
                float r2 = fmaf(dx, dx, fmaf(dy, dy, fmaf(dz, dz, EPSF)));
                float rinv = rsqrt_mufu(r2);
                float sr  = (lsi.x + lsj.x) * rinv;
                float sr2 = sr * sr;
                float sr6 = sr2 * sr2 * sr2;
                float tt  = fmaf(sr6, sr6, -sr6);        // sr12 - sr6
                acc += fmaf(lsi.y * lsj.y, tt, pqi.w * pqj.w * rinv);
            }
        } else {
            // diagonal tile: only j > li
#pragma unroll 8
            for (int j = 0; j < TILE; j++) {
                float4 pqj = spq[j];
                float2 lsj = sls[j];
                float dx = pqi.x - pqj.x;
                float dy = pqi.y - pqj.y;
                float dz = pqi.z - pqj.z;
                float r2 = fmaf(dx, dx, fmaf(dy, dy, fmaf(dz, dz, EPSF)));
                bool valid = (j > li);
                r2 = valid ? r2 : 1.0f;
                float rinv = rsqrt_mufu(r2);
                float sr  = (lsi.x + lsj.x) * rinv;
                float sr2 = sr * sr;
                float sr6 = sr2 * sr2 * sr2;
                float tt  = fmaf(sr6, sr6, -sr6);
                float e   = fmaf(lsi.y * lsj.y, tt, pqi.w * pqj.w * rinv);
                acc += valid ? e : 0.0f;
            }
        }
    } else {
        // ---- bonded terms + mask correction ----
        int gid = (blockIdx.x - NPAIRBLK) * TILE + threadIdx.x;
        acc = bonded_body(gid, pos, q, eps, sig, sb_mask, bond_c, angle_c,
                          anglec_c, dih_c, dihc_c, imp_c, bond_i, angle_i,
                          anglec_i, dih_i, dihc_i, imp_i);
    }

    // block reduce -> one double atomic per block
    for (int off = 16; off; off >>= 1)
        acc += __shfl_down_sync(0xffffffffu, acc, off);
    __shared__ float wsum[TILE / 32];
    if ((threadIdx.x & 31) == 0) wsum[threadIdx.x >> 5] = acc;
    __syncthreads();
    if (threadIdx.x == 0) {
        double s = 0.0;
#pragma unroll
        for (int w = 0; w < TILE / 32; w++) s += (double)wsum[w];
        atomicAdd(&g_acc, s);
    }

    // ---- last-block-done: emit result and restore all scratch to zero ----
    __shared__ bool is_last;
    if (threadIdx.x == 0) {
        __threadfence();
        unsigned done = atomicAdd(&g_count, 1u);
        is_last = (done == NBLK_MAIN - 1);
    }
    __syncthreads();
    if (is_last) {
        __threadfence();   // make all blocks' g_acc / g_hash writes visible
        for (int k = threadIdx.x; k < HASH_SIZE; k += TILE)
            g_hash[k] = 0u;
        if (threadIdx.x == 0) {
            double total = *((volatile double*)&g_acc);
            out[0] = (float)total;
            g_acc = 0.0;
            g_count = 0u;
        }
    }
}

// ---------------- launch ----------------
extern "C" void kernel_launch(void* const* d_in, const int* in_sizes, int n_in,
                              void* d_out, int out_size) {
    const float* atom_pos    = (const float*)d_in[0];
    const float* atom_charge = (const float*)d_in[1];
    const float* epsilon     = (const float*)d_in[2];
    const float* sigma       = (const float*)d_in[3];
    const float* sb_mask     = (const float*)d_in[4];
    const float* bond_c      = (const float*)d_in[5];
    const float* angle_c     = (const float*)d_in[6];
    const float* anglec_c    = (const float*)d_in[7];
    const float* dih_c       = (const float*)d_in[8];
    const float* dihc_c      = (const float*)d_in[9];
    const float* imp_c       = (const float*)d_in[10];
    const int* bond_i   = (const int*)d_in[11];
    const int* angle_i  = (const int*)d_in[12];
    const int* anglec_i = (const int*)d_in[13];
    const int* dih_i    = (const int*)d_in[14];
    const int* dihc_i   = (const int*)d_in[15];
    const int* imp_i    = (const int*)d_in[16];
    // d_in[17] = pair_idx: deliberately unused (it is just triu_indices(NA,1))

    k_main<<<NBLK_MAIN, TILE>>>((float*)d_out,
                                atom_pos, atom_charge, epsilon, sigma, sb_mask,
                                bond_c, angle_c, anglec_c, dih_c, dihc_c, imp_c,
                                bond_i, angle_i, anglec_i, dih_i, dihc_i, imp_i);
}

// round 6
// speedup vs baseline: 1.3282x; 1.3282x over previous
#include <cuda_runtime.h>

// ---------------- problem constants (fixed by the dataset) ----------------
#define NA    4096
#define NB    4000
#define NANG  8000
#define NAC   4000
#define ND    12000
#define NDC   6000
#define NI    2000
#define TILE  128
#define NTILE (NA / TILE)                    // 32
#define NPAIRBLK (NTILE * (NTILE + 1) / 2)   // 528
#define COULF 332.33f
#define EPSF  1e-12f

#define ANG_OFF   (NB)                       // 4000
#define ANGC_OFF  (ANG_OFF + NANG)           // 12000
#define DIH_OFF   (ANGC_OFF + NAC)           // 16000
#define DIHC_OFF  (DIH_OFF + ND)             // 28000
#define IMP_OFF   (DIHC_OFF + NDC)           // 34000
#define CORR_OFF  (IMP_OFF + NI)             // 36000
#define NCORR     (NB + NANG)                // 12000
#define TOT_BONDED (CORR_OFF + NCORR)        // 48000
#define BBLK      256
#define NBONDBLK  ((TOT_BONDED + BBLK - 1) / BBLK)   // 188

#define HASH_BITS 15
#define HASH_SIZE (1 << HASH_BITS)           // 32768 entries, ~12000 used

// ---------------- device scratch (static, allocation-free) ----------------
__device__ double       g_acc;
__device__ unsigned int g_count;
__device__ float4       g_posq[NA];          // x,y,z, q*sqrt(COULOMB)
__device__ float2       g_ls[NA];            // 0.5*sigma, 2*sqrt(eps)
__device__ unsigned int g_hash[HASH_SIZE];   // dedup hash set, cleared each call by k_init

// ---------------- math helpers ----------------
__device__ __forceinline__ float rsqrt_raw(float x) {
    // raw MUFU.RSQ: ~2^-22 rel err; x12 LJ amplification -> ~2e-6, far under 1e-3 tol
    float y;
    asm("rsqrt.approx.f32 %0, %1;" : "=f"(y) : "f"(x));
    return y;
}

struct f3 { float x, y, z; };
__device__ __forceinline__ f3 ldp(const float* p, int i) {
    return { p[3 * i], p[3 * i + 1], p[3 * i + 2] };
}
__device__ __forceinline__ f3 f3sub(f3 a, f3 b) { return { a.x - b.x, a.y - b.y, a.z - b.z }; }
__device__ __forceinline__ float f3dot(f3 a, f3 b) { return a.x * b.x + a.y * b.y + a.z * b.z; }
__device__ __forceinline__ f3 f3cross(f3 a, f3 b) {
    return { a.y * b.z - a.z * b.y, a.z * b.x - a.x * b.z, a.x * b.y - a.y * b.x };
}

__device__ __forceinline__ float angle3(f3 p0, f3 p1, f3 p2) {
    f3 u = f3sub(p0, p1);
    f3 v = f3sub(p2, p1);
    float c = f3dot(u, v) / sqrtf(f3dot(u, u) * f3dot(v, v) + EPSF);
    c = fminf(fmaxf(c, -1.0f + 1e-7f), 1.0f - 1e-7f);
    return acosf(c);
}

__device__ __forceinline__ float dihedral_phi(f3 p0, f3 p1, f3 p2, f3 p3) {
    f3 b1 = f3sub(p1, p0);
    f3 b2 = f3sub(p2, p1);
    f3 b3 = f3sub(p3, p2);
    f3 n1 = f3cross(b1, b2);
    f3 n2 = f3cross(b2, b3);
    float bl = sqrtf(f3dot(b2, b2) + EPSF);
    f3 b2n = { b2.x / bl, b2.y / bl, b2.z / bl };
    float yv = f3dot(f3cross(n1, b2n), n2);
    float xv = f3dot(n1, n2);
    return atan2f(yv, xv);
}

// LJ + Coulomb pair energy from precomputed per-atom data (matches the pair loop)
__device__ __forceinline__ float pair_energy(int i, int j) {
    float4 a = g_posq[i], b = g_posq[j];
    float2 la = g_ls[i],  lb = g_ls[j];
    float dx = a.x - b.x, dy = a.y - b.y, dz = a.z - b.z;
    float r2 = fmaf(dx, dx, fmaf(dy, dy, fmaf(dz, dz, EPSF)));
    float rinv = rsqrt_raw(r2);
    float sr  = (la.x + lb.x) * rinv;
    float sr2 = sr * sr;
    float sr6 = sr2 * sr2 * sr2;
    float t   = fmaf(sr6, sr6, -sr6);        // sr12 - sr6
    return fmaf(la.y * lb.y, t, a.w * b.w * rinv);
}

// ---------------- kernel 1: init accumulator, per-atom data, clear hash ----------------
__global__ void k_init(const float* __restrict__ pos, const float* __restrict__ q,
                       const float* __restrict__ eps, const float* __restrict__ sig) {
    int i = blockIdx.x * blockDim.x + threadIdx.x;   // 0..4095
    if (i == 0) { g_acc = 0.0; g_count = 0u; }
    g_posq[i] = make_float4(pos[3 * i], pos[3 * i + 1], pos[3 * i + 2],
                            q[i] * sqrtf(COULF));
    g_ls[i] = make_float2(0.5f * sig[i], 2.0f * sqrtf(eps[i]));
#pragma unroll
    for (int k = 0; k < HASH_SIZE / NA; k++)         // 8 sequential stores/thread
        g_hash[i + k * NA] = 0u;
}

// ---------------- kernel 2: all-pairs LJ + Coulomb ----------------
__global__ void __launch_bounds__(TILE) k_pairs() {
    __shared__ float4 spq[TILE];
    __shared__ float2 sls[TILE];

    // decode linear block id -> (bi, bj) with bi <= bj (upper-triangle tiles)
    int t = blockIdx.x;
    int bi = 0, rowlen = NTILE;
    while (t >= rowlen) { t -= rowlen; rowlen--; bi++; }
    int bj = bi + t;

    int li = threadIdx.x;
    float4 pqi = g_posq[bi * TILE + li];
    float2 lsi = g_ls[bi * TILE + li];
    spq[li] = g_posq[bj * TILE + li];
    sls[li] = g_ls[bj * TILE + li];
    __syncthreads();

    float accA = 0.0f;   // LJ term accumulator
    float accB = 0.0f;   // Coulomb term accumulator

    if (bi != bj) {
#pragma unroll 8
        for (int j = 0; j < TILE; j++) {
            float4 pqj = spq[j];
            float2 lsj = sls[j];
            float dx = pqi.x - pqj.x;
            float dy = pqi.y - pqj.y;
            float dz = pqi.z - pqj.z;
            float r2 = fmaf(dx, dx, fmaf(dy, dy, fmaf(dz, dz, EPSF)));
            float rinv = rsqrt_raw(r2);
            float sr  = (lsi.x + lsj.x) * rinv;
            float sr2 = sr * sr;
            float sr6 = sr2 * sr2 * sr2;
            float tt  = fmaf(sr6, sr6, -sr6);            // sr12 - sr6
            accA = fmaf(lsi.y * lsj.y, tt, accA);
            accB = fmaf(pqi.w * pqj.w, rinv, accB);
        }
    } else {
        // diagonal tile: only j > li counts; zeroing rinv zeroes both energy terms
#pragma unroll 8
        for (int j = 0; j < TILE; j++) {
            float4 pqj = spq[j];
            float2 lsj = sls[j];
            float dx = pqi.x - pqj.x;
            float dy = pqi.y - pqj.y;
            float dz = pqi.z - pqj.z;
            float r2 = fmaf(dx, dx, fmaf(dy, dy, fmaf(dz, dz, EPSF)));
            float rinv = rsqrt_raw(r2);
            rinv = (j > li) ? rinv : 0.0f;               // single select
            float sr  = (lsi.x + lsj.x) * rinv;
            float sr2 = sr * sr;
            float sr6 = sr2 * sr2 * sr2;
            float tt  = fmaf(sr6, sr6, -sr6);
            accA = fmaf(lsi.y * lsj.y, tt, accA);
            accB = fmaf(pqi.w * pqj.w, rinv, accB);
        }
    }

    float acc = accA + accB;
    for (int off = 16; off; off >>= 1)
        acc += __shfl_down_sync(0xffffffffu, acc, off);
    __shared__ float wsum[TILE / 32];
    if ((threadIdx.x & 31) == 0) wsum[threadIdx.x >> 5] = acc;
    __syncthreads();
    if (threadIdx.x == 0) {
        double s = 0.0;
#pragma unroll
        for (int w = 0; w < TILE / 32; w++) s += (double)wsum[w];
        atomicAdd(&g_acc, s);
    }
}

// ---------------- kernel 3: bonded terms + mask correction + final emit ----------------
__global__ void __launch_bounds__(BBLK) k_bonded(
    float* __restrict__ out,
    const float* __restrict__ pos,
    const float* __restrict__ sb_mask,
    const float* __restrict__ bond_c, const float* __restrict__ angle_c,
    const float* __restrict__ anglec_c, const float* __restrict__ dih_c,
    const float* __restrict__ dihc_c, const float* __restrict__ imp_c,
    const int* __restrict__ bond_i, const int* __restrict__ angle_i,
    const int* __restrict__ anglec_i, const int* __restrict__ dih_i,
    const int* __restrict__ dihc_i, const int* __restrict__ imp_i)
{
    int gid = blockIdx.x * blockDim.x + threadIdx.x;
    float e = 0.0f;

    if (gid < ANG_OFF) {
        const int* b = bond_i + 3 * gid;
        int i = b[0], j = b[1], ty = b[2];
        f3 d = f3sub(ldp(pos, i), ldp(pos, j));
        float r = sqrtf(f3dot(d, d) + EPSF);
        float dr = r - bond_c[2 * ty + 1];
        e = bond_c[2 * ty] * dr * dr;
    } else if (gid < ANGC_OFF) {
        int k = gid - ANG_OFF;
        const int* a = angle_i + 4 * k;
        int ty = a[3];
        float th = angle3(ldp(pos, a[0]), ldp(pos, a[1]), ldp(pos, a[2]));
        float dth = th - angle_c[2 * ty + 1];
        e = angle_c[2 * ty] * dth * dth;
    } else if (gid < DIH_OFF) {
        int k = gid - ANGC_OFF;
        const int* a = anglec_i + 4 * k;
        int ty = a[3];
        f3 p0 = ldp(pos, a[0]), p1 = ldp(pos, a[1]), p2 = ldp(pos, a[2]);
        float th = angle3(p0, p1, p2);
        f3 d02 = f3sub(p0, p2);
        float r13 = sqrtf(f3dot(d02, d02) + EPSF);
        const float* c = anglec_c + 4 * ty;
        float dth = th - c[1];
        float dr  = r13 - c[3];
        e = c[0] * dth * dth + c[2] * dr * dr;
    } else if (gid < DIHC_OFF) {
        int k = gid - DIH_OFF;
        const int* a = dih_i + 5 * k;
        int ty = a[4];
        float phi = dihedral_phi(ldp(pos, a[0]), ldp(pos, a[1]),
                                 ldp(pos, a[2]), ldp(pos, a[3]));
        float c = cosf(phi);
        const float* A = dih_c + 5 * ty;
        e = A[0] + c * (A[1] + c * (A[2] + c * (A[3] + c * A[4])));
    } else if (gid < IMP_OFF) {
        int k = gid - DIHC_OFF;
        const int* a = dihc_i + 5 * k;
        int ty = a[4];
        float phi = dihedral_phi(ldp(pos, a[0]), ldp(pos, a[1]),
                                 ldp(pos, a[2]), ldp(pos, a[3]));
        const float* c = dihc_c + 4 * ty;
        e = c[0] * (1.0f + cosf(c[1] * phi - c[2]));
    } else if (gid < CORR_OFF) {
        int k = gid - IMP_OFF;
        const int* a = imp_i + 5 * k;
        int ty = a[4];
        float chi = dihedral_phi(ldp(pos, a[0]), ldp(pos, a[1]),
                                 ldp(pos, a[2]), ldp(pos, a[3]));
        float d = chi - imp_c[2 * ty + 1];
        e = imp_c[2 * ty] * d * d;
    } else if (gid < TOT_BONDED) {
        // mask==0 correction: candidates = bond pairs + angle 1-3 pairs.
        // Subtract each distinct masked pair's energy exactly once (hash-set dedup).
        int c = gid - CORR_OFF;
        int iu, iv;
        if (c < NB) { iu = bond_i[3 * c]; iv = bond_i[3 * c + 1]; }
        else        { int a = c - NB; iu = angle_i[4 * a]; iv = angle_i[4 * a + 2]; }
        if (iu != iv) {
            int lo = min(iu, iv), hi = max(iu, iv);
            if (sb_mask[(size_t)lo * NA + hi] == 0.0f) {
                unsigned key = ((unsigned)lo << 12) | (unsigned)hi;   // nonzero (lo<hi)
                unsigned h = (key * 2654435761u) >> (32 - HASH_BITS);
                bool first = false;
                for (;;) {
                    unsigned old = atomicCAS(&g_hash[h], 0u, key);
                    if (old == 0u) { first = true; break; }
                    if (old == key) break;
                    h = (h + 1) & (HASH_SIZE - 1);
                }
                if (first) e = -pair_energy(lo, hi);
            }
        }
    }

    // block reduce -> one double atomic per block
    for (int off = 16; off; off >>= 1)
        e += __shfl_down_sync(0xffffffffu, e, off);
    __shared__ float wsum[BBLK / 32];
    if ((threadIdx.x & 31) == 0) wsum[threadIdx.x >> 5] = e;
    __syncthreads();

    if (threadIdx.x == 0) {
        double s = 0.0;
#pragma unroll
        for (int w = 0; w < BBLK / 32; w++) s += (double)wsum[w];
        atomicAdd(&g_acc, s);

        // last-block-done: k_pairs finished before this kernel started (stream
        // order), so once all bonded blocks' atomics are in, emit the result.
        __threadfence();
        unsigned done = atomicAdd(&g_count, 1u);
        if (done == NBONDBLK - 1) {
            double total = atomicAdd(&g_acc, 0.0);   // coherent L2 read
            out[0] = (float)total;
        }
    }
}

// ---------------- launch ----------------
extern "C" void kernel_launch(void* const* d_in, const int* in_sizes, int n_in,
                              void* d_out, int out_size) {
    const float* atom_pos    = (const float*)d_in[0];
    const float* atom_charge = (const float*)d_in[1];
    const float* epsilon     = (const float*)d_in[2];
    const float* sigma       = (const float*)d_in[3];
    const float* sb_mask     = (const float*)d_in[4];
    const float* bond_c      = (const float*)d_in[5];
    const float* angle_c     = (const float*)d_in[6];
    const float* anglec_c    = (const float*)d_in[7];
    const float* dih_c       = (const float*)d_in[8];
    const float* dihc_c      = (const float*)d_in[9];
    const float* imp_c       = (const float*)d_in[10];
    const int* bond_i   = (const int*)d_in[11];
    const int* angle_i  = (const int*)d_in[12];
    const int* anglec_i = (const int*)d_in[13];
    const int* dih_i    = (const int*)d_in[14];
    const int* dihc_i   = (const int*)d_in[15];
    const int* imp_i    = (const int*)d_in[16];
    // d_in[17] = pair_idx: deliberately unused (it is just triu_indices(NA,1))

    k_init<<<NA / TILE, TILE>>>(atom_pos, atom_charge, epsilon, sigma);
    k_pairs<<<NPAIRBLK, TILE>>>();
    k_bonded<<<NBONDBLK, BBLK>>>((float*)d_out,
                                 atom_pos, sb_mask, bond_c, angle_c, anglec_c,
                                 dih_c, dihc_c, imp_c, bond_i, angle_i, anglec_i,
                                 dih_i, dihc_i, imp_i);
}

// round 7
// speedup vs baseline: 1.5686x; 1.1810x over previous
#include <cuda_runtime.h>

// ---------------- problem constants (fixed by the dataset) ----------------
#define NA    4096
#define NB    4000
#define NANG  8000
#define NAC   4000
#define ND    12000
#define NDC   6000
#define NI    2000
#define TILE  128
#define NTILE (NA / TILE)                    // 32
#define NPAIRBLK (NTILE * (NTILE + 1) / 2)   // 528
#define COULF 332.33f
#define EPSF  1e-12f

#define ANG_OFF   (NB)                       // 4000
#define ANGC_OFF  (ANG_OFF + NANG)           // 12000
#define DIH_OFF   (ANGC_OFF + NAC)           // 16000
#define DIHC_OFF  (DIH_OFF + ND)             // 28000
#define IMP_OFF   (DIHC_OFF + NDC)           // 34000
#define CORR_OFF  (IMP_OFF + NI)             // 36000
#define NCORR     (NB + NANG)                // 12000
#define TOT_BONDED (CORR_OFF + NCORR)        // 48000
#define NBONDBLK  ((TOT_BONDED + TILE - 1) / TILE)  // 375
#define NBLK_MAIN (NPAIRBLK + NBONDBLK)             // 903

#define HASH_BITS 15
#define HASH_SIZE (1 << HASH_BITS)           // 32768 entries, ~12000 used

// ---------------- device scratch (static, allocation-free) ----------------
__device__ double       g_acc;
__device__ float4       g_posq[NA];          // x,y,z, q*sqrt(COULOMB)
__device__ float2       g_ls[NA];            // 0.5*sigma, 2*sqrt(eps)
__device__ unsigned int g_hash[HASH_SIZE];   // dedup hash set, cleared each call by k_init

// ---------------- math helpers ----------------
__device__ __forceinline__ float rsqrt_raw(float x) {
    // raw MUFU.RSQ (validated in R5: rel_err unchanged at 1.04e-7)
    float y;
    asm("rsqrt.approx.f32 %0, %1;" : "=f"(y) : "f"(x));
    return y;
}

struct f3 { float x, y, z; };
__device__ __forceinline__ f3 ldp(const float* p, int i) {
    return { p[3 * i], p[3 * i + 1], p[3 * i + 2] };
}
__device__ __forceinline__ f3 f3sub(f3 a, f3 b) { return { a.x - b.x, a.y - b.y, a.z - b.z }; }
__device__ __forceinline__ float f3dot(f3 a, f3 b) { return a.x * b.x + a.y * b.y + a.z * b.z; }
__device__ __forceinline__ f3 f3cross(f3 a, f3 b) {
    return { a.y * b.z - a.z * b.y, a.z * b.x - a.x * b.z, a.x * b.y - a.y * b.x };
}

__device__ __forceinline__ float angle3(f3 p0, f3 p1, f3 p2) {
    f3 u = f3sub(p0, p1);
    f3 v = f3sub(p2, p1);
    float c = f3dot(u, v) / sqrtf(f3dot(u, u) * f3dot(v, v) + EPSF);
    c = fminf(fmaxf(c, -1.0f + 1e-7f), 1.0f - 1e-7f);
    return acosf(c);
}

__device__ __forceinline__ float dihedral_phi(f3 p0, f3 p1, f3 p2, f3 p3) {
    f3 b1 = f3sub(p1, p0);
    f3 b2 = f3sub(p2, p1);
    f3 b3 = f3sub(p3, p2);
    f3 n1 = f3cross(b1, b2);
    f3 n2 = f3cross(b2, b3);
    float bl = sqrtf(f3dot(b2, b2) + EPSF);
    f3 b2n = { b2.x / bl, b2.y / bl, b2.z / bl };
    float yv = f3dot(f3cross(n1, b2n), n2);
    float xv = f3dot(n1, n2);
    return atan2f(yv, xv);
}

// LJ + Coulomb pair energy from precomputed per-atom data (matches the pair loop)
__device__ __forceinline__ float pair_energy(int i, int j) {
    float4 a = g_posq[i], b = g_posq[j];
    float2 la = g_ls[i],  lb = g_ls[j];
    float dx = a.x - b.x, dy = a.y - b.y, dz = a.z - b.z;
    float r2 = fmaf(dx, dx, fmaf(dy, dy, fmaf(dz, dz, EPSF)));
    float rinv = rsqrt_raw(r2);
    float sr  = (la.x + lb.x) * rinv;
    float sr2 = sr * sr;
    float sr6 = sr2 * sr2 * sr2;
    float t   = fmaf(sr6, sr6, -sr6);        // sr12 - sr6
    return fmaf(la.y * lb.y, t, a.w * b.w * rinv);
}

// ---------------- kernel 1: init accumulator, per-atom data, clear hash ----------------
__global__ void __launch_bounds__(256) k_init(
    const float* __restrict__ pos, const float* __restrict__ q,
    const float* __restrict__ eps, const float* __restrict__ sig)
{
    int i = blockIdx.x * blockDim.x + threadIdx.x;   // 0..32767
    if (i == 0) g_acc = 0.0;
    if (i < NA) {
        g_posq[i] = make_float4(pos[3 * i], pos[3 * i + 1], pos[3 * i + 2],
                                q[i] * sqrtf(COULF));
        g_ls[i] = make_float2(0.5f * sig[i], 2.0f * sqrtf(eps[i]));
    }
    g_hash[i] = 0u;                                   // one store per thread
}

// ---------------- bonded + correction thread body ----------------
__device__ __forceinline__ float bonded_body(
    int gid,
    const float* __restrict__ pos,
    const float* __restrict__ sb_mask,
    const float* __restrict__ bond_c, const float* __restrict__ angle_c,
    const float* __restrict__ anglec_c, const float* __restrict__ dih_c,
    const float* __restrict__ dihc_c, const float* __restrict__ imp_c,
    const int* __restrict__ bond_i, const int* __restrict__ angle_i,
    const int* __restrict__ anglec_i, const int* __restrict__ dih_i,
    const int* __restrict__ dihc_i, const int* __restrict__ imp_i)
{
    float e = 0.0f;
    if (gid < ANG_OFF) {
        const int* b = bond_i + 3 * gid;
        int i = b[0], j = b[1], ty = b[2];
        f3 d = f3sub(ldp(pos, i), ldp(pos, j));
        float r = sqrtf(f3dot(d, d) + EPSF);
        float dr = r - bond_c[2 * ty + 1];
        e = bond_c[2 * ty] * dr * dr;
    } else if (gid < ANGC_OFF) {
        int k = gid - ANG_OFF;
        const int* a = angle_i + 4 * k;
        int ty = a[3];
        float th = angle3(ldp(pos, a[0]), ldp(pos, a[1]), ldp(pos, a[2]));
        float dth = th - angle_c[2 * ty + 1];
        e = angle_c[2 * ty] * dth * dth;
    } else if (gid < DIH_OFF) {
        int k = gid - ANGC_OFF;
        const int* a = anglec_i + 4 * k;
        int ty = a[3];
        f3 p0 = ldp(pos, a[0]), p1 = ldp(pos, a[1]), p2 = ldp(pos, a[2]);
        float th = angle3(p0, p1, p2);
        f3 d02 = f3sub(p0, p2);
        float r13 = sqrtf(f3dot(d02, d02) + EPSF);
        const float* c = anglec_c + 4 * ty;
        float dth = th - c[1];
        float dr  = r13 - c[3];
        e = c[0] * dth * dth + c[2] * dr * dr;
    } else if (gid < DIHC_OFF) {
        int k = gid - DIH_OFF;
        const int* a = dih_i + 5 * k;
        int ty = a[4];
        float phi = dihedral_phi(ldp(pos, a[0]), ldp(pos, a[1]),
                                 ldp(pos, a[2]), ldp(pos, a[3]));
        float c = cosf(phi);
        const float* A = dih_c + 5 * ty;
        e = A[0] + c * (A[1] + c * (A[2] + c * (A[3] + c * A[4])));
    } else if (gid < IMP_OFF) {
        int k = gid - DIHC_OFF;
        const int* a = dihc_i + 5 * k;
        int ty = a[4];
        float phi = dihedral_phi(ldp(pos, a[0]), ldp(pos, a[1]),
                                 ldp(pos, a[2]), ldp(pos, a[3]));
        const float* c = dihc_c + 4 * ty;
        e = c[0] * (1.0f + cosf(c[1] * phi - c[2]));
    } else if (gid < CORR_OFF) {
        int k = gid - IMP_OFF;
        const int* a = imp_i + 5 * k;
        int ty = a[4];
        float chi = dihedral_phi(ldp(pos, a[0]), ldp(pos, a[1]),
                                 ldp(pos, a[2]), ldp(pos, a[3]));
        float d = chi - imp_c[2 * ty + 1];
        e = imp_c[2 * ty] * d * d;
    } else if (gid < TOT_BONDED) {
        // mask==0 correction: candidates = bond pairs + angle 1-3 pairs.
        // Subtract each distinct masked pair's energy exactly once (hash-set dedup).
        int c = gid - CORR_OFF;
        int iu, iv;
        if (c < NB) { iu = bond_i[3 * c]; iv = bond_i[3 * c + 1]; }
        else        { int a = c - NB; iu = angle_i[4 * a]; iv = angle_i[4 * a + 2]; }
        if (iu != iv) {
            int lo = min(iu, iv), hi = max(iu, iv);
            if (sb_mask[(size_t)lo * NA + hi] == 0.0f) {
                unsigned key = ((unsigned)lo << 12) | (unsigned)hi;   // nonzero (lo<hi)
                unsigned h = (key * 2654435761u) >> (32 - HASH_BITS);
                bool first = false;
                for (;;) {
                    unsigned old = atomicCAS(&g_hash[h], 0u, key);
                    if (old == 0u) { first = true; break; }
                    if (old == key) break;
                    h = (h + 1) & (HASH_SIZE - 1);
                }
                if (first) e = -pair_energy(lo, hi);
            }
        }
    }
    return e;
}

// ---------------- kernel 2: fused pairs (blocks 0..527) + bonded (528..902) ----------------
__global__ void __launch_bounds__(TILE) k_main(
    const float* __restrict__ pos,
    const float* __restrict__ sb_mask,
    const float* __restrict__ bond_c, const float* __restrict__ angle_c,
    const float* __restrict__ anglec_c, const float* __restrict__ dih_c,
    const float* __restrict__ dihc_c, const float* __restrict__ imp_c,
    const int* __restrict__ bond_i, const int* __restrict__ angle_i,
    const int* __restrict__ anglec_i, const int* __restrict__ dih_i,
    const int* __restrict__ dihc_i, const int* __restrict__ imp_i)
{
    float acc = 0.0f;

    if (blockIdx.x < NPAIRBLK) {
        // ---- all-pairs LJ + Coulomb over one 128x128 tile ----
        __shared__ float4 spq[TILE];
        __shared__ float2 sls[TILE];

        int t = blockIdx.x;
        int bi = 0, rowlen = NTILE;
        while (t >= rowlen) { t -= rowlen; rowlen--; bi++; }
        int bj = bi + t;

        int li = threadIdx.x;
        float4 pqi = g_posq[bi * TILE + li];
        float2 lsi = g_ls[bi * TILE + li];
        spq[li] = g_posq[bj * TILE + li];
        sls[li] = g_ls[bj * TILE + li];
        __syncthreads();

        float accA = 0.0f;   // sum_j lsj.y * (sr12 - sr6)   (scaled by lsi.y after)
        float accB = 0.0f;   // sum_j pqj.w * rinv           (scaled by pqi.w after)

        if (bi != bj) {
#pragma unroll 8
            for (int j = 0; j < TILE; j++) {
                float4 pqj = spq[j];
                float2 lsj = sls[j];
                float dx = pqi.x - pqj.x;
                float dy = pqi.y - pqj.y;
                float dz = pqi.z - pqj.z;
                float r2 = fmaf(dx, dx, fmaf(dy, dy, fmaf(dz, dz, EPSF)));
                float rinv = rsqrt_raw(r2);
                float sr  = (lsi.x + lsj.x) * rinv;
                float sr2 = sr * sr;
                float sr6 = sr2 * sr2 * sr2;
                float tt  = fmaf(sr6, sr6, -sr6);        // sr12 - sr6
                accA = fmaf(lsj.y, tt, accA);
                accB = fmaf(pqj.w, rinv, accB);
            }
        } else {
            // diagonal tile: only j > li; zeroing rinv zeroes both energy terms
#pragma unroll 8
            for (int j = 0; j < TILE; j++) {
                float4 pqj = spq[j];
                float2 lsj = sls[j];
                float dx = pqi.x - pqj.x;
                float dy = pqi.y - pqj.y;
                float dz = pqi.z - pqj.z;
                float r2 = fmaf(dx, dx, fmaf(dy, dy, fmaf(dz, dz, EPSF)));
                float rinv = rsqrt_raw(r2);
                rinv = (j > li) ? rinv : 0.0f;           // single select
                float sr  = (lsi.x + lsj.x) * rinv;
                float sr2 = sr * sr;
                float sr6 = sr2 * sr2 * sr2;
                float tt  = fmaf(sr6, sr6, -sr6);
                accA = fmaf(lsj.y, tt, accA);
                accB = fmaf(pqj.w, rinv, accB);
            }
        }
        acc = fmaf(lsi.y, accA, pqi.w * accB);
    } else {
        // ---- bonded terms + mask correction (runs concurrently with pair blocks) ----
        int gid = (blockIdx.x - NPAIRBLK) * TILE + threadIdx.x;
        acc = bonded_body(gid, pos, sb_mask, bond_c, angle_c, anglec_c, dih_c,
                          dihc_c, imp_c, bond_i, angle_i, anglec_i, dih_i,
                          dihc_i, imp_i);
    }

    // block reduce -> one double atomic per block
    for (int off = 16; off; off >>= 1)
        acc += __shfl_down_sync(0xffffffffu, acc, off);
    __shared__ float wsum[TILE / 32];
    if ((threadIdx.x & 31) == 0) wsum[threadIdx.x >> 5] = acc;
    __syncthreads();
    if (threadIdx.x == 0) {
        double s = 0.0;
#pragma unroll
        for (int w = 0; w < TILE / 32; w++) s += (double)wsum[w];
        atomicAdd(&g_acc, s);
    }
}

// ---------------- kernel 3: emit result ----------------
__global__ void k_final(float* __restrict__ out) {
    out[0] = (float)g_acc;
}

// ---------------- launch ----------------
extern "C" void kernel_launch(void* const* d_in, const int* in_sizes, int n_in,
                              void* d_out, int out_size) {
    const float* atom_pos    = (const float*)d_in[0];
    const float* atom_charge = (const float*)d_in[1];
    const float* epsilon     = (const float*)d_in[2];
    const float* sigma       = (const float*)d_in[3];
    const float* sb_mask     = (const float*)d_in[4];
    const float* bond_c      = (const float*)d_in[5];
    const float* angle_c     = (const float*)d_in[6];
    const float* anglec_c    = (const float*)d_in[7];
    const float* dih_c       = (const float*)d_in[8];
    const float* dihc_c      = (const float*)d_in[9];
    const float* imp_c       = (const float*)d_in[10];
    const int* bond_i   = (const int*)d_in[11];
    const int* angle_i  = (const int*)d_in[12];
    const int* anglec_i = (const int*)d_in[13];
    const int* dih_i    = (const int*)d_in[14];
    const int* dihc_i   = (const int*)d_in[15];
    const int* imp_i    = (const int*)d_in[16];
    // d_in[17] = pair_idx: deliberately unused (it is just triu_indices(NA,1))

    k_init<<<HASH_SIZE / 256, 256>>>(atom_pos, atom_charge, epsilon, sigma);
    k_main<<<NBLK_MAIN, TILE>>>(atom_pos, sb_mask, bond_c, angle_c, anglec_c,
                                dih_c, dihc_c, imp_c, bond_i, angle_i, anglec_i,
                                dih_i, dihc_i, imp_i);
    k_final<<<1, 1>>>((float*)d_out);
}

// round 8
// speedup vs baseline: 1.5854x; 1.0107x over previous
#include <cuda_runtime.h>

// ---------------- problem constants (fixed by the dataset) ----------------
#define NA    4096
#define NB    4000
#define NANG  8000
#define NAC   4000
#define ND    12000
#define NDC   6000
#define NI    2000
#define TILE  128
#define NTILE (NA / TILE)                    // 32
#define NPAIRBLK (NTILE * (NTILE + 1) / 2)   // 528
#define COULF 332.33f
#define EPSF  1e-12f

#define ANG_OFF   (NB)                       // 4000
#define ANGC_OFF  (ANG_OFF + NANG)           // 12000
#define DIH_OFF   (ANGC_OFF + NAC)           // 16000
#define DIHC_OFF  (DIH_OFF + ND)             // 28000
#define IMP_OFF   (DIHC_OFF + NDC)           // 34000
#define CORR_OFF  (IMP_OFF + NI)             // 36000
#define NCORR     (NB + NANG)                // 12000
#define TOT_BONDED (CORR_OFF + NCORR)        // 48000
#define NBONDBLK  ((TOT_BONDED + TILE - 1) / TILE)  // 375
#define NBLK_MAIN (NPAIRBLK + NBONDBLK)             // 903

#define HASH_BITS 15
#define HASH_SIZE (1 << HASH_BITS)           // 32768 entries, ~12000 used

// ---------------- device scratch (static, allocation-free) ----------------
__device__ double       g_acc;
__device__ unsigned int g_count;
__device__ float4       g_posq[NA];          // x,y,z, q*sqrt(COULOMB)
__device__ float2       g_ls[NA];            // 0.5*sigma, 2*sqrt(eps)
__device__ unsigned int g_hash[HASH_SIZE];   // dedup hash set, cleared each call by k_init

// ---------------- math helpers ----------------
__device__ __forceinline__ float rsqrt_raw(float x) {
    // raw MUFU.RSQ (validated: rel_err stays at 1.04e-7)
    float y;
    asm("rsqrt.approx.f32 %0, %1;" : "=f"(y) : "f"(x));
    return y;
}

struct f3 { float x, y, z; };
__device__ __forceinline__ f3 ldp(const float* p, int i) {
    return { p[3 * i], p[3 * i + 1], p[3 * i + 2] };
}
__device__ __forceinline__ f3 f3sub(f3 a, f3 b) { return { a.x - b.x, a.y - b.y, a.z - b.z }; }
__device__ __forceinline__ float f3dot(f3 a, f3 b) { return a.x * b.x + a.y * b.y + a.z * b.z; }
__device__ __forceinline__ f3 f3cross(f3 a, f3 b) {
    return { a.y * b.z - a.z * b.y, a.z * b.x - a.x * b.z, a.x * b.y - a.y * b.x };
}

__device__ __forceinline__ float angle3(f3 p0, f3 p1, f3 p2) {
    f3 u = f3sub(p0, p1);
    f3 v = f3sub(p2, p1);
    float c = f3dot(u, v) / sqrtf(f3dot(u, u) * f3dot(v, v) + EPSF);
    c = fminf(fmaxf(c, -1.0f + 1e-7f), 1.0f - 1e-7f);
    return acosf(c);
}

__device__ __forceinline__ float dihedral_phi(f3 p0, f3 p1, f3 p2, f3 p3) {
    f3 b1 = f3sub(p1, p0);
    f3 b2 = f3sub(p2, p1);
    f3 b3 = f3sub(p3, p2);
    f3 n1 = f3cross(b1, b2);
    f3 n2 = f3cross(b2, b3);
    float bl = sqrtf(f3dot(b2, b2) + EPSF);
    f3 b2n = { b2.x / bl, b2.y / bl, b2.z / bl };
    float yv = f3dot(f3cross(n1, b2n), n2);
    float xv = f3dot(n1, n2);
    return atan2f(yv, xv);
}

// LJ + Coulomb pair energy from precomputed per-atom data (matches the pair loop)
__device__ __forceinline__ float pair_energy(int i, int j) {
    float4 a = g_posq[i], b = g_posq[j];
    float2 la = g_ls[i],  lb = g_ls[j];
    float dx = a.x - b.x, dy = a.y - b.y, dz = a.z - b.z;
    float r2 = fmaf(dx, dx, fmaf(dy, dy, fmaf(dz, dz, EPSF)));
    float rinv = rsqrt_raw(r2);
    float sr  = (la.x + lb.x) * rinv;
    float sr2 = sr * sr;
    float sr6 = sr2 * sr2 * sr2;
    float t   = fmaf(sr6, sr6, -sr6);        // sr12 - sr6
    return fmaf(la.y * lb.y, t, a.w * b.w * rinv);
}

// ---------------- kernel 1: init accumulators, per-atom data, clear hash ----------------
__global__ void __launch_bounds__(256) k_init(
    const float* __restrict__ pos, const float* __restrict__ q,
    const float* __restrict__ eps, const float* __restrict__ sig)
{
    int i = blockIdx.x * blockDim.x + threadIdx.x;   // 0..32767
    if (i == 0) { g_acc = 0.0; g_count = 0u; }
    if (i < NA) {
        g_posq[i] = make_float4(pos[3 * i], pos[3 * i + 1], pos[3 * i + 2],
                                q[i] * sqrtf(COULF));
        g_ls[i] = make_float2(0.5f * sig[i], 2.0f * sqrtf(eps[i]));
    }
    g_hash[i] = 0u;                                   // one store per thread
}

// ---------------- bonded + correction thread body ----------------
__device__ __forceinline__ float bonded_body(
    int gid,
    const float* __restrict__ pos,
    const float* __restrict__ sb_mask,
    const float* __restrict__ bond_c, const float* __restrict__ angle_c,
    const float* __restrict__ anglec_c, const float* __restrict__ dih_c,
    const float* __restrict__ dihc_c, const float* __restrict__ imp_c,
    const int* __restrict__ bond_i, const int* __restrict__ angle_i,
    const int* __restrict__ anglec_i, const int* __restrict__ dih_i,
    const int* __restrict__ dihc_i, const int* __restrict__ imp_i)
{
    float e = 0.0f;
    if (gid < ANG_OFF) {
        const int* b = bond_i + 3 * gid;
        int i = b[0], j = b[1], ty = b[2];
        f3 d = f3sub(ldp(pos, i), ldp(pos, j));
        float r = sqrtf(f3dot(d, d) + EPSF);
        float dr = r - bond_c[2 * ty + 1];
        e = bond_c[2 * ty] * dr * dr;
    } else if (gid < ANGC_OFF) {
        int k = gid - ANG_OFF;
        const int* a = angle_i + 4 * k;
        int ty = a[3];
        float th = angle3(ldp(pos, a[0]), ldp(pos, a[1]), ldp(pos, a[2]));
        float dth = th - angle_c[2 * ty + 1];
        e = angle_c[2 * ty] * dth * dth;
    } else if (gid < DIH_OFF) {
        int k = gid - ANGC_OFF;
        const int* a = anglec_i + 4 * k;
        int ty = a[3];
        f3 p0 = ldp(pos, a[0]), p1 = ldp(pos, a[1]), p2 = ldp(pos, a[2]);
        float th = angle3(p0, p1, p2);
        f3 d02 = f3sub(p0, p2);
        float r13 = sqrtf(f3dot(d02, d02) + EPSF);
        const float* c = anglec_c + 4 * ty;
        float dth = th - c[1];
        float dr  = r13 - c[3];
        e = c[0] * dth * dth + c[2] * dr * dr;
    } else if (gid < DIHC_OFF) {
        int k = gid - DIH_OFF;
        const int* a = dih_i + 5 * k;
        int ty = a[4];
        float phi = dihedral_phi(ldp(pos, a[0]), ldp(pos, a[1]),
                                 ldp(pos, a[2]), ldp(pos, a[3]));
        float c = cosf(phi);
        const float* A = dih_c + 5 * ty;
        e = A[0] + c * (A[1] + c * (A[2] + c * (A[3] + c * A[4])));
    } else if (gid < IMP_OFF) {
        int k = gid - DIHC_OFF;
        const int* a = dihc_i + 5 * k;
        int ty = a[4];
        float phi = dihedral_phi(ldp(pos, a[0]), ldp(pos, a[1]),
                                 ldp(pos, a[2]), ldp(pos, a[3]));
        const float* c = dihc_c + 4 * ty;
        e = c[0] * (1.0f + cosf(c[1] * phi - c[2]));
    } else if (gid < CORR_OFF) {
        int k = gid - IMP_OFF;
        const int* a = imp_i + 5 * k;
        int ty = a[4];
        float chi = dihedral_phi(ldp(pos, a[0]), ldp(pos, a[1]),
                                 ldp(pos, a[2]), ldp(pos, a[3]));
        float d = chi - imp_c[2 * ty + 1];
        e = imp_c[2 * ty] * d * d;
    } else if (gid < TOT_BONDED) {
        // mask==0 correction: candidates = bond pairs + angle 1-3 pairs.
        // Subtract each distinct masked pair's energy exactly once (hash-set dedup).
        int c = gid - CORR_OFF;
        int iu, iv;
        if (c < NB) { iu = bond_i[3 * c]; iv = bond_i[3 * c + 1]; }
        else        { int a = c - NB; iu = angle_i[4 * a]; iv = angle_i[4 * a + 2]; }
        if (iu != iv) {
            int lo = min(iu, iv), hi = max(iu, iv);
            if (sb_mask[(size_t)lo * NA + hi] == 0.0f) {
                unsigned key = ((unsigned)lo << 12) | (unsigned)hi;   // nonzero (lo<hi)
                unsigned h = (key * 2654435761u) >> (32 - HASH_BITS);
                bool first = false;
                for (;;) {
                    unsigned old = atomicCAS(&g_hash[h], 0u, key);
                    if (old == 0u) { first = true; break; }
                    if (old == key) break;
                    h = (h + 1) & (HASH_SIZE - 1);
                }
                if (first) e = -pair_energy(lo, hi);
            }
        }
    }
    return e;
}

// ---------------- kernel 2: fused pairs + bonded + final emit ----------------
__global__ void __launch_bounds__(TILE) k_main(
    float* __restrict__ out,
    const float* __restrict__ pos,
    const float* __restrict__ sb_mask,
    const float* __restrict__ bond_c, const float* __restrict__ angle_c,
    const float* __restrict__ anglec_c, const float* __restrict__ dih_c,
    const float* __restrict__ dihc_c, const float* __restrict__ imp_c,
    const int* __restrict__ bond_i, const int* __restrict__ angle_i,
    const int* __restrict__ anglec_i, const int* __restrict__ dih_i,
    const int* __restrict__ dihc_i, const int* __restrict__ imp_i)
{
    float acc = 0.0f;

    if (blockIdx.x < NPAIRBLK) {
        // ---- all-pairs LJ + Coulomb over one 128x128 tile ----
        __shared__ float4 spq[TILE];
        __shared__ float2 sls[TILE];

        int t = blockIdx.x;
        int bi = 0, rowlen = NTILE;
        while (t >= rowlen) { t -= rowlen; rowlen--; bi++; }
        int bj = bi + t;

        int li = threadIdx.x;
        float4 pqi = g_posq[bi * TILE + li];
        float2 lsi = g_ls[bi * TILE + li];
        spq[li] = g_posq[bj * TILE + li];
        sls[li] = g_ls[bj * TILE + li];
        __syncthreads();

        float accA = 0.0f;   // sum_j lsj.y * (sr12 - sr6)   (scaled by lsi.y after)
        float accB = 0.0f;   // sum_j pqj.w * rinv           (scaled by pqi.w after)

        if (bi != bj) {
#pragma unroll 8
            for (int j = 0; j < TILE; j++) {
                float4 pqj = spq[j];
                float2 lsj = sls[j];
                float dx = pqi.x - pqj.x;
                float dy = pqi.y - pqj.y;
                float dz = pqi.z - pqj.z;
                float r2 = fmaf(dx, dx, fmaf(dy, dy, fmaf(dz, dz, EPSF)));
                float rinv = rsqrt_raw(r2);
                float sr  = (lsi.x + lsj.x) * rinv;
                float sr2 = sr * sr;
                float sr6 = sr2 * sr2 * sr2;
                float tt  = fmaf(sr6, sr6, -sr6);        // sr12 - sr6
                accA = fmaf(lsj.y, tt, accA);
                accB = fmaf(pqj.w, rinv, accB);
            }
        } else {
            // diagonal tile: only j > li; zeroing rinv zeroes both energy terms
#pragma unroll 8
            for (int j = 0; j < TILE; j++) {
                float4 pqj = spq[j];
                float2 lsj = sls[j];
                float dx = pqi.x - pqj.x;
                float dy = pqi.y - pqj.y;
                float dz = pqi.z - pqj.z;
                float r2 = fmaf(dx, dx, fmaf(dy, dy, fmaf(dz, dz, EPSF)));
                float rinv = rsqrt_raw(r2);
                rinv = (j > li) ? rinv : 0.0f;           // single select
                float sr  = (lsi.x + lsj.x) * rinv;
                float sr2 = sr * sr;
                float sr6 = sr2 * sr2 * sr2;
                float tt  = fmaf(sr6, sr6, -sr6);
                accA = fmaf(lsj.y, tt, accA);
                accB = fmaf(pqj.w, rinv, accB);
            }
        }
        acc = fmaf(lsi.y, accA, pqi.w * accB);
    } else {
        // ---- bonded terms + mask correction (runs concurrently with pair blocks) ----
        int gid = (blockIdx.x - NPAIRBLK) * TILE + threadIdx.x;
        acc = bonded_body(gid, pos, sb_mask, bond_c, angle_c, anglec_c, dih_c,
                          dihc_c, imp_c, bond_i, angle_i, anglec_i, dih_i,
                          dihc_i, imp_i);
    }

    // block reduce -> one double atomic per block
    for (int off = 16; off; off >>= 1)
        acc += __shfl_down_sync(0xffffffffu, acc, off);
    __shared__ float wsum[TILE / 32];
    if ((threadIdx.x & 31) == 0) wsum[threadIdx.x >> 5] = acc;
    __syncthreads();
    if (threadIdx.x == 0) {
        double s = 0.0;
#pragma unroll
        for (int w = 0; w < TILE / 32; w++) s += (double)wsum[w];
        atomicAdd(&g_acc, s);

        // last-block-done: emit the result (replaces the k_final node).
        __threadfence();
        unsigned done = atomicAdd(&g_count, 1u);
        if (done == NBLK_MAIN - 1) {
            double total = atomicAdd(&g_acc, 0.0);   // coherent read after all atomics
            out[0] = (float)total;
        }
    }
}

// ---------------- launch ----------------
extern "C" void kernel_launch(void* const* d_in, const int* in_sizes, int n_in,
                              void* d_out, int out_size) {
    const float* atom_pos    = (const float*)d_in[0];
    const float* atom_charge = (const float*)d_in[1];
    const float* epsilon     = (const float*)d_in[2];
    const float* sigma       = (const float*)d_in[3];
    const float* sb_mask     = (const float*)d_in[4];
    const float* bond_c      = (const float*)d_in[5];
    const float* angle_c     = (const float*)d_in[6];
    const float* anglec_c    = (const float*)d_in[7];
    const float* dih_c       = (const float*)d_in[8];
    const float* dihc_c      = (const float*)d_in[9];
    const float* imp_c       = (const float*)d_in[10];
    const int* bond_i   = (const int*)d_in[11];
    const int* angle_i  = (const int*)d_in[12];
    const int* anglec_i = (const int*)d_in[13];
    const int* dih_i    = (const int*)d_in[14];
    const int* dihc_i   = (const int*)d_in[15];
    const int* imp_i    = (const int*)d_in[16];
    // d_in[17] = pair_idx: deliberately unused (it is just triu_indices(NA,1))

    k_init<<<HASH_SIZE / 256, 256>>>(atom_pos, atom_charge, epsilon, sigma);
    k_main<<<NBLK_MAIN, TILE>>>((float*)d_out,
                                atom_pos, sb_mask, bond_c, angle_c, anglec_c,
                                dih_c, dihc_c, imp_c, bond_i, angle_i, anglec_i,
                                dih_i, dihc_i, imp_i);
}

// round 9
// speedup vs baseline: 1.9697x; 1.2424x over previous
#include <cuda_runtime.h>

// ---------------- problem constants (fixed by the dataset) ----------------
#define NA    4096
#define NB    4000
#define NANG  8000
#define NAC   4000
#define ND    12000
#define NDC   6000
#define NI    2000
#define TILE  128
#define NTILE (NA / TILE)                    // 32
#define NPAIRBLK (NTILE * (NTILE + 1) / 2)   // 528
#define COULF 332.33f
#define EPSF  1e-12f

#define ANG_OFF   (NB)                       // 4000
#define ANGC_OFF  (ANG_OFF + NANG)           // 12000
#define DIH_OFF   (ANGC_OFF + NAC)           // 16000
#define DIHC_OFF  (DIH_OFF + ND)             // 28000
#define IMP_OFF   (DIHC_OFF + NDC)           // 34000
#define CORR_OFF  (IMP_OFF + NI)             // 36000
#define NCORR     (NB + NANG)                // 12000
#define TOT_BONDED (CORR_OFF + NCORR)        // 48000
#define NBONDBLK  ((TOT_BONDED + TILE - 1) / TILE)  // 375
#define NBLK_MAIN (NPAIRBLK + NBONDBLK)             // 903

#define HASH_BITS 15
#define HASH_SIZE (1 << HASH_BITS)           // 32768 entries, ~12000 used

typedef unsigned long long u64;

// ---------------- device scratch (static, allocation-free) ----------------
__device__ double       g_acc;
__device__ unsigned int g_count;
__device__ float4       g_posq[NA];          // x,y,z, q*sqrt(COULOMB)
__device__ float2       g_ls[NA];            // 0.5*sigma, 2*sqrt(eps)
__device__ unsigned int g_hash[HASH_SIZE];   // dedup hash set, cleared each call by k_init

// ---------------- packed f32x2 helpers (sm_103a FFMA2 path, PTX-only) ----------------
__device__ __forceinline__ u64 f2_pack(float lo, float hi) {
    u64 r; asm("mov.b64 %0, {%1, %2};" : "=l"(r) : "f"(lo), "f"(hi)); return r;
}
__device__ __forceinline__ void f2_unpack(u64 p, float& lo, float& hi) {
    asm("mov.b64 {%0, %1}, %2;" : "=f"(lo), "=f"(hi) : "l"(p));
}
__device__ __forceinline__ u64 f2_add(u64 a, u64 b) {
    u64 r; asm("add.rn.f32x2 %0, %1, %2;" : "=l"(r) : "l"(a), "l"(b)); return r;
}
__device__ __forceinline__ u64 f2_mul(u64 a, u64 b) {
    u64 r; asm("mul.rn.f32x2 %0, %1, %2;" : "=l"(r) : "l"(a), "l"(b)); return r;
}
__device__ __forceinline__ u64 f2_fma(u64 a, u64 b, u64 c) {
    u64 r; asm("fma.rn.f32x2 %0, %1, %2, %3;" : "=l"(r) : "l"(a), "l"(b), "l"(c)); return r;
}
__device__ __forceinline__ u64 f2_neg(u64 a) { return a ^ 0x8000000080000000ULL; }

// ---------------- math helpers ----------------
__device__ __forceinline__ float rsqrt_raw(float x) {
    float y;
    asm("rsqrt.approx.f32 %0, %1;" : "=f"(y) : "f"(x));
    return y;
}

struct f3 { float x, y, z; };
__device__ __forceinline__ f3 ldp(const float* p, int i) {
    return { p[3 * i], p[3 * i + 1], p[3 * i + 2] };
}
__device__ __forceinline__ f3 f3sub(f3 a, f3 b) { return { a.x - b.x, a.y - b.y, a.z - b.z }; }
__device__ __forceinline__ float f3dot(f3 a, f3 b) { return a.x * b.x + a.y * b.y + a.z * b.z; }
__device__ __forceinline__ f3 f3cross(f3 a, f3 b) {
    return { a.y * b.z - a.z * b.y, a.z * b.x - a.x * b.z, a.x * b.y - a.y * b.x };
}

__device__ __forceinline__ float angle3(f3 p0, f3 p1, f3 p2) {
    f3 u = f3sub(p0, p1);
    f3 v = f3sub(p2, p1);
    float c = f3dot(u, v) / sqrtf(f3dot(u, u) * f3dot(v, v) + EPSF);
    c = fminf(fmaxf(c, -1.0f + 1e-7f), 1.0f - 1e-7f);
    return acosf(c);
}

__device__ __forceinline__ float dihedral_phi(f3 p0, f3 p1, f3 p2, f3 p3) {
    f3 b1 = f3sub(p1, p0);
    f3 b2 = f3sub(p2, p1);
    f3 b3 = f3sub(p3, p2);
    f3 n1 = f3cross(b1, b2);
    f3 n2 = f3cross(b2, b3);
    float bl = sqrtf(f3dot(b2, b2) + EPSF);
    f3 b2n = { b2.x / bl, b2.y / bl, b2.z / bl };
    float yv = f3dot(f3cross(n1, b2n), n2);
    float xv = f3dot(n1, n2);
    return atan2f(yv, xv);
}

// LJ + Coulomb pair energy from precomputed per-atom data
__device__ __forceinline__ float pair_energy(int i, int j) {
    float4 a = g_posq[i], b = g_posq[j];
    float2 la = g_ls[i],  lb = g_ls[j];
    float dx = a.x - b.x, dy = a.y - b.y, dz = a.z - b.z;
    float r2 = fmaf(dx, dx, fmaf(dy, dy, fmaf(dz, dz, EPSF)));
    float rinv = rsqrt_raw(r2);
    float sr  = (la.x + lb.x) * rinv;
    float sr2 = sr * sr;
    float sr6 = sr2 * sr2 * sr2;
    float t   = fmaf(sr6, sr6, -sr6);        // sr12 - sr6
    return fmaf(la.y * lb.y, t, a.w * b.w * rinv);
}

// ---------------- kernel 1: init accumulators, per-atom data, clear hash ----------------
__global__ void __launch_bounds__(256) k_init(
    const float* __restrict__ pos, const float* __restrict__ q,
    const float* __restrict__ eps, const float* __restrict__ sig)
{
    int i = blockIdx.x * blockDim.x + threadIdx.x;   // 0..32767
    if (i == 0) { g_acc = 0.0; g_count = 0u; }
    if (i < NA) {
        g_posq[i] = make_float4(pos[3 * i], pos[3 * i + 1], pos[3 * i + 2],
                                q[i] * sqrtf(COULF));
        g_ls[i] = make_float2(0.5f * sig[i], 2.0f * sqrtf(eps[i]));
    }
    g_hash[i] = 0u;                                   // one store per thread
}

// ---------------- bonded + correction thread body ----------------
__device__ __forceinline__ float bonded_body(
    int gid,
    const float* __restrict__ pos,
    const float* __restrict__ sb_mask,
    const float* __restrict__ bond_c, const float* __restrict__ angle_c,
    const float* __restrict__ anglec_c, const float* __restrict__ dih_c,
    const float* __restrict__ dihc_c, const float* __restrict__ imp_c,
    const int* __restrict__ bond_i, const int* __restrict__ angle_i,
    const int* __restrict__ anglec_i, const int* __restrict__ dih_i,
    const int* __restrict__ dihc_i, const int* __restrict__ imp_i)
{
    float e = 0.0f;
    if (gid < ANG_OFF) {
        const int* b = bond_i + 3 * gid;
        int i = b[0], j = b[1], ty = b[2];
        f3 d = f3sub(ldp(pos, i), ldp(pos, j));
        float r = sqrtf(f3dot(d, d) + EPSF);
        float dr = r - bond_c[2 * ty + 1];
        e = bond_c[2 * ty] * dr * dr;
    } else if (gid < ANGC_OFF) {
        int k = gid - ANG_OFF;
        const int* a = angle_i + 4 * k;
        int ty = a[3];
        float th = angle3(ldp(pos, a[0]), ldp(pos, a[1]), ldp(pos, a[2]));
        float dth = th - angle_c[2 * ty + 1];
        e = angle_c[2 * ty] * dth * dth;
    } else if (gid < DIH_OFF) {
        int k = gid - ANGC_OFF;
        const int* a = anglec_i + 4 * k;
        int ty = a[3];
        f3 p0 = ldp(pos, a[0]), p1 = ldp(pos, a[1]), p2 = ldp(pos, a[2]);
        float th = angle3(p0, p1, p2);
        f3 d02 = f3sub(p0, p2);
        float r13 = sqrtf(f3dot(d02, d02) + EPSF);
        const float* c = anglec_c + 4 * ty;
        float dth = th - c[1];
        float dr  = r13 - c[3];
        e = c[0] * dth * dth + c[2] * dr * dr;
    } else if (gid < DIHC_OFF) {
        int k = gid - DIH_OFF;
        const int* a = dih_i + 5 * k;
        int ty = a[4];
        float phi = dihedral_phi(ldp(pos, a[0]), ldp(pos, a[1]),
                                 ldp(pos, a[2]), ldp(pos, a[3]));
        float c = cosf(phi);
        const float* A = dih_c + 5 * ty;
        e = A[0] + c * (A[1] + c * (A[2] + c * (A[3] + c * A[4])));
    } else if (gid < IMP_OFF) {
        int k = gid - DIHC_OFF;
        const int* a = dihc_i + 5 * k;
        int ty = a[4];
        float phi = dihedral_phi(ldp(pos, a[0]), ldp(pos, a[1]),
                                 ldp(pos, a[2]), ldp(pos, a[3]));
        const float* c = dihc_c + 4 * ty;
        e = c[0] * (1.0f + cosf(c[1] * phi - c[2]));
    } else if (gid < CORR_OFF) {
        int k = gid - IMP_OFF;
        const int* a = imp_i + 5 * k;
        int ty = a[4];
        float chi = dihedral_phi(ldp(pos, a[0]), ldp(pos, a[1]),
                                 ldp(pos, a[2]), ldp(pos, a[3]));
        float d = chi - imp_c[2 * ty + 1];
        e = imp_c[2 * ty] * d * d;
    } else if (gid < TOT_BONDED) {
        // mask==0 correction: candidates = bond pairs + angle 1-3 pairs.
        // Subtract each distinct masked pair's energy exactly once (hash-set dedup).
        int c = gid - CORR_OFF;
        int iu, iv;
        if (c < NB) { iu = bond_i[3 * c]; iv = bond_i[3 * c + 1]; }
        else        { int a = c - NB; iu = angle_i[4 * a]; iv = angle_i[4 * a + 2]; }
        if (iu != iv) {
            int lo = min(iu, iv), hi = max(iu, iv);
            if (sb_mask[(size_t)lo * NA + hi] == 0.0f) {
                unsigned key = ((unsigned)lo << 12) | (unsigned)hi;   // nonzero (lo<hi)
                unsigned h = (key * 2654435761u) >> (32 - HASH_BITS);
                bool first = false;
                for (;;) {
                    unsigned old = atomicCAS(&g_hash[h], 0u, key);
                    if (old == 0u) { first = true; break; }
                    if (old == key) break;
                    h = (h + 1) & (HASH_SIZE - 1);
                }
                if (first) e = -pair_energy(lo, hi);
            }
        }
    }
    return e;
}

// ---------------- packed pair loop (2 j-atoms per iteration) ----------------
// SMEM layout per packed pair jj (j=2jj, j'=2jj+1):
//   sA[jj] = { pack(-x_j, -x_j'), pack(-y_j, -y_j') }
//   sB[jj] = { pack(-z_j, -z_j'), pack( w_j,  w_j') }
//   sC[jj] = { pack( s_j,  s_j'), pack( e_j,  e_j') }
template<bool DIAG>
__device__ __forceinline__ void pair_loop(
    const ulonglong2* __restrict__ sA, const ulonglong2* __restrict__ sB,
    const ulonglong2* __restrict__ sC,
    u64 xi2, u64 yi2, u64 zi2, u64 si2, int li,
    u64& accA, u64& accB)
{
    const u64 eps2 = f2_pack(EPSF, EPSF);
#pragma unroll 8
    for (int jj = 0; jj < TILE / 2; jj++) {
        ulonglong2 va = sA[jj];
        ulonglong2 vb = sB[jj];
        ulonglong2 vc = sC[jj];
        u64 dx = f2_add(xi2, va.x);
        u64 dy = f2_add(yi2, va.y);
        u64 dz = f2_add(zi2, vb.x);
        u64 r2 = f2_fma(dx, dx, eps2);
        r2 = f2_fma(dy, dy, r2);
        r2 = f2_fma(dz, dz, r2);
        float r2a, r2b;
        f2_unpack(r2, r2a, r2b);
        float ra = rsqrt_raw(r2a);
        float rb = rsqrt_raw(r2b);
        if (DIAG) {
            ra = (2 * jj     > li) ? ra : 0.0f;   // zero rinv zeroes both terms
            rb = (2 * jj + 1 > li) ? rb : 0.0f;
        }
        u64 rinv = f2_pack(ra, rb);
        u64 s   = f2_add(si2, vc.x);
        u64 sr  = f2_mul(s, rinv);
        u64 sr2 = f2_mul(sr, sr);
        u64 sr4 = f2_mul(sr2, sr2);
        u64 sr6 = f2_mul(sr4, sr2);
        u64 tt  = f2_fma(sr6, sr6, f2_neg(sr6));   // sr12 - sr6
        accA = f2_fma(vc.y, tt, accA);
        accB = f2_fma(vb.y, rinv, accB);
    }
}

// ---------------- kernel 2: fused pairs + bonded + final emit ----------------
__global__ void __launch_bounds__(TILE) k_main(
    float* __restrict__ out,
    const float* __restrict__ pos,
    const float* __restrict__ sb_mask,
    const float* __restrict__ bond_c, const float* __restrict__ angle_c,
    const float* __restrict__ anglec_c, const float* __restrict__ dih_c,
    const float* __restrict__ dihc_c, const float* __restrict__ imp_c,
    const int* __restrict__ bond_i, const int* __restrict__ angle_i,
    const int* __restrict__ anglec_i, const int* __restrict__ dih_i,
    const int* __restrict__ dihc_i, const int* __restrict__ imp_i)
{
    float acc = 0.0f;

    if (blockIdx.x < NPAIRBLK) {
        // ---- all-pairs LJ + Coulomb over one 128x128 tile, packed 2-wide ----
        __shared__ ulonglong2 sA[TILE / 2];
        __shared__ ulonglong2 sB[TILE / 2];
        __shared__ ulonglong2 sC[TILE / 2];

        int t = blockIdx.x;
        int bi = 0, rowlen = NTILE;
        while (t >= rowlen) { t -= rowlen; rowlen--; bi++; }
        int bj = bi + t;

        int li = threadIdx.x;
        float4 pqi = g_posq[bi * TILE + li];
        float2 lsi = g_ls[bi * TILE + li];

        // fill packed SMEM: thread li owns j-atom li
        {
            float4 pqj = g_posq[bj * TILE + li];
            float2 lsj = g_ls[bj * TILE + li];
            int jj = li >> 1, h = li & 1;
            float* fA = (float*)sA;
            float* fB = (float*)sB;
            float* fC = (float*)sC;
            fA[4 * jj + h]     = -pqj.x;
            fA[4 * jj + 2 + h] = -pqj.y;
            fB[4 * jj + h]     = -pqj.z;
            fB[4 * jj + 2 + h] =  pqj.w;
            fC[4 * jj + h]     =  lsj.x;
            fC[4 * jj + 2 + h] =  lsj.y;
        }
        __syncthreads();

        u64 xi2 = f2_pack(pqi.x, pqi.x);
        u64 yi2 = f2_pack(pqi.y, pqi.y);
        u64 zi2 = f2_pack(pqi.z, pqi.z);
        u64 si2 = f2_pack(lsi.x, lsi.x);
        u64 accA = 0ULL;   // packed sum_j e_j * (sr12 - sr6)
        u64 accB = 0ULL;   // packed sum_j w_j * rinv

        if (bi != bj)
            pair_loop<false>(sA, sB, sC, xi2, yi2, zi2, si2, li, accA, accB);
        else
            pair_loop<true >(sA, sB, sC, xi2, yi2, zi2, si2, li, accA, accB);

        float aA0, aA1, aB0, aB1;
        f2_unpack(accA, aA0, aA1);
        f2_unpack(accB, aB0, aB1);
        acc = fmaf(lsi.y, aA0 + aA1, pqi.w * (aB0 + aB1));
    } else {
        // ---- bonded terms + mask correction (runs concurrently with pair blocks) ----
        int gid = (blockIdx.x - NPAIRBLK) * TILE + threadIdx.x;
        acc = bonded_body(gid, pos, sb_mask, bond_c, angle_c, anglec_c, dih_c,
                          dihc_c, imp_c, bond_i, angle_i, anglec_i, dih_i,
                          dihc_i, imp_i);
    }

    // block reduce -> one double atomic per block
    for (int off = 16; off; off >>= 1)
        acc += __shfl_down_sync(0xffffffffu, acc, off);
    __shared__ float wsum[TILE / 32];
    if ((threadIdx.x & 31) == 0) wsum[threadIdx.x >> 5] = acc;
    __syncthreads();
    if (threadIdx.x == 0) {
        double s = 0.0;
#pragma unroll
        for (int w = 0; w < TILE / 32; w++) s += (double)wsum[w];
        atomicAdd(&g_acc, s);

        // last-block-done: emit the result
        __threadfence();
        unsigned done = atomicAdd(&g_count, 1u);
        if (done == NBLK_MAIN - 1) {
            double total = atomicAdd(&g_acc, 0.0);   // coherent read after all atomics
            out[0] = (float)total;
        }
    }
}

// ---------------- launch ----------------
extern "C" void kernel_launch(void* const* d_in, const int* in_sizes, int n_in,
                              void* d_out, int out_size) {
    const float* atom_pos    = (const float*)d_in[0];
    const float* atom_charge = (const float*)d_in[1];
    const float* epsilon     = (const float*)d_in[2];
    const float* sigma       = (const float*)d_in[3];
    const float* sb_mask     = (const float*)d_in[4];
    const float* bond_c      = (const float*)d_in[5];
    const float* angle_c     = (const float*)d_in[6];
    const float* anglec_c    = (const float*)d_in[7];
    const float* dih_c       = (const float*)d_in[8];
    const float* dihc_c      = (const float*)d_in[9];
    const float* imp_c       = (const float*)d_in[10];
    const int* bond_i   = (const int*)d_in[11];
    const int* angle_i  = (const int*)d_in[12];
    const int* anglec_i = (const int*)d_in[13];
    const int* dih_i    = (const int*)d_in[14];
    const int* dihc_i   = (const int*)d_in[15];
    const int* imp_i    = (const int*)d_in[16];
    // d_in[17] = pair_idx: deliberately unused (it is just triu_indices(NA,1))

    k_init<<<HASH_SIZE / 256, 256>>>(atom_pos, atom_charge, epsilon, sigma);
    k_main<<<NBLK_MAIN, TILE>>>((float*)d_out,
                                atom_pos, sb_mask, bond_c, angle_c, anglec_c,
                                dih_c, dihc_c, imp_c, bond_i, angle_i, anglec_i,
                                dih_i, dihc_i, imp_i);
}